// round 14
// baseline (speedup 1.0000x reference)
#include <cuda_runtime.h>
#include <cuda_fp16.h>
#include <math.h>
#include <stdint.h>

#define BS     32
#define TT     20               // targets per batch
#define GW     76               // grid width/height
#define PLANE  (GW*GW)          // 5776
#define QPB    (3*PLANE/4)      // cell-quads per batch = 4332
#define BPB    17               // blocks per batch = ceil(4332/256)
#define MAIN_BLOCKS (BS*BPB)    // 544
#define TGT_BLOCKS  80          // 80 x 8 warps = 640 warps = BS*TT
#define GRID_TOT (MAIN_BLOCKS + TGT_BLOCKS)  // 624 -> single wave
#define NC     80

// scaled anchors = ANCHORS / 8
__constant__ float c_aw9[9] = {1.5f, 2.375f, 5.0f, 4.5f, 9.5f, 9.0f, 17.75f, 24.0f, 57.375f};
__constant__ float c_ah9[9] = {2.0f, 4.5f,  3.5f, 9.375f, 6.875f, 18.25f, 13.75f, 30.375f, 50.125f};
// level-2 anchors (mask [0,1,2])
__constant__ float c_aw3[3] = {1.5f, 2.375f, 5.0f};
__constant__ float c_ah3[3] = {2.0f, 4.5f,  3.5f};

// zero-init at load; finalizer resets after each run (graph-replay safe)
__device__ double       g_acc[5];   // 0:loc 1:nobj 2:cls 3:conf 4:mask
__device__ unsigned int g_done;

__device__ __forceinline__ float softplusf_(float z) {
    float az = fabsf(z);
    return fmaxf(z, 0.0f) + __logf(1.0f + __expf(-az));
}
__device__ __forceinline__ float sigmoidf_(float x) {
    return __fdividef(1.0f, 1.0f + __expf(-x));
}

// prep one target: returns cell (-1 if not this level) and gt geometry
__device__ __forceinline__ int prep_target(const float* __restrict__ p,
                                           float& gx, float& gy, float& gw, float& gh) {
    gx = p[0] * (float)GW; gy = p[1] * (float)GW;
    gw = p[2] * (float)GW; gh = p[3] * (float)GW;
    float bestr = -1e30f; int best = 0;
    #pragma unroll
    for (int n = 0; n < 9; n++) {
        float inter = fminf(gw, c_aw9[n]) * fminf(gh, c_ah9[n]);
        float uni   = gw * gh + c_aw9[n] * c_ah9[n] - inter;
        float r = inter / uni;   // exact divide: argmax ties matter
        if (r > bestr) { bestr = r; best = n; }
    }
    if (best >= 3) return -1;    // l=2: anchors_mask [0,1,2]
    int gi = min(max((int)floorf(gx), 0), GW - 1);
    int gj = min(max((int)floorf(gy), 0), GW - 1);
    return best * PLANE + gj * GW + gi;
}

__device__ __forceinline__ void finish_block(float* out) {
    __syncthreads();
    if (threadIdx.x == 0) {
        __threadfence();
        unsigned int v = atomicAdd(&g_done, 1u);
        if (v == GRID_TOT - 1) {
            __threadfence();
            double a0 = g_acc[0], a1 = g_acc[1], a2 = g_acc[2];
            double a3 = g_acc[3], a4 = g_acc[4];
            g_acc[0]=0.0; g_acc[1]=0.0; g_acc[2]=0.0; g_acc[3]=0.0; g_acc[4]=0.0;
            g_done = 0u;
            double n     = a1 > 1.0 ? a1 : 1.0;
            double cmask = a4 > 1.0 ? a4 : 1.0;
            const double OBJ_RATIO = 5.0 * 608.0 * 608.0 / (416.0 * 416.0);
            const double BAL = 4.0;   // BALANCE[2]
            double loss = a0 / n * 0.05
                        + a2 / (n * (double)NC)
                        + a3 / cmask * BAL * OBJ_RATIO;
            out[0] = (float)loss;
        }
    }
}

struct __align__(16) GtH { __half2 lx, ly, rx, ry; };

__global__ void __launch_bounds__(256) k_fused(const float* __restrict__ in,
                                               const float* __restrict__ tgt,
                                               float* __restrict__ out)
{
    const int tid = threadIdx.x;

    if (blockIdx.x < MAIN_BLOCKS) {
        // ===== main path: noobj conf BCE + fp16x2 ignore test, 4 cells/thread =====
        __shared__ GtH    s_gth[TT];    // gt corners, splatted half2
        __shared__ __half2 s_nga[TT];   // half2(-ga,-ga)

        const int b = blockIdx.x / BPB;
        const int q = (blockIdx.x % BPB) * 256 + tid;

        if (tid < TT) {
            const float* p = tgt + (b * TT + tid) * 5;
            float gx = p[0] * (float)GW, gy = p[1] * (float)GW;
            float gw = p[2] * (float)GW, gh = p[3] * (float)GW;
            GtH g;
            g.lx = __float2half2_rn(gx - 0.5f * gw);
            g.ly = __float2half2_rn(gy - 0.5f * gh);
            g.rx = __float2half2_rn(gx + 0.5f * gw);
            g.ry = __float2half2_rn(gy + 0.5f * gh);
            s_gth[tid] = g;
            s_nga[tid] = __float2half2_rn(-(gw * gh));
        }
        __syncthreads();

        float cl = 0.0f, cm = 0.0f;
        if (q < QPB) {
            int c0  = 4 * q;
            int a   = c0 / PLANE;
            int rem = c0 - a * PLANE;            // multiple of 4; row-aligned (GW%4==0)
            int j   = rem / GW;
            int i0  = rem - j * GW;

            const float* base = in + ((b * 255 + a * 85) * PLANE + rem);
            float4 rx = *(const float4*)(base);
            float4 ry = *(const float4*)(base + PLANE);
            float4 rw = *(const float4*)(base + 2 * PLANE);
            float4 rh = *(const float4*)(base + 3 * PLANE);
            float4 rc = *(const float4*)(base + 4 * PLANE);

            const float aw = c_aw3[a], ah = c_ah3[a];
            const float fj = (float)j;

            float px0 = (float)(i0+0) + sigmoidf_(rx.x);
            float px1 = (float)(i0+1) + sigmoidf_(rx.y);
            float px2 = (float)(i0+2) + sigmoidf_(rx.z);
            float px3 = (float)(i0+3) + sigmoidf_(rx.w);
            float py0 = fj + sigmoidf_(ry.x);
            float py1 = fj + sigmoidf_(ry.y);
            float py2 = fj + sigmoidf_(ry.z);
            float py3 = fj + sigmoidf_(ry.w);
            float pw0 = __expf(rw.x) * aw, pw1 = __expf(rw.y) * aw;
            float pw2 = __expf(rw.z) * aw, pw3 = __expf(rw.w) * aw;
            float ph0 = __expf(rh.x) * ah, ph1 = __expf(rh.y) * ah;
            float ph2 = __expf(rh.z) * ah, ph3 = __expf(rh.w) * ah;

            // pack corners as half2 cell-pairs
            __half2 lX01 = __floats2half2_rn(px0 - 0.5f*pw0, px1 - 0.5f*pw1);
            __half2 lX23 = __floats2half2_rn(px2 - 0.5f*pw2, px3 - 0.5f*pw3);
            __half2 rX01 = __floats2half2_rn(px0 + 0.5f*pw0, px1 + 0.5f*pw1);
            __half2 rX23 = __floats2half2_rn(px2 + 0.5f*pw2, px3 + 0.5f*pw3);
            __half2 lY01 = __floats2half2_rn(py0 - 0.5f*ph0, py1 - 0.5f*ph1);
            __half2 lY23 = __floats2half2_rn(py2 - 0.5f*ph2, py3 - 0.5f*ph3);
            __half2 rY01 = __floats2half2_rn(py0 + 0.5f*ph0, py1 + 0.5f*ph1);
            __half2 rY23 = __floats2half2_rn(py2 + 0.5f*ph2, py3 + 0.5f*ph3);
            __half2 pa01 = __floats2half2_rn(pw0*ph0, pw1*ph1);
            __half2 pa23 = __floats2half2_rn(pw2*ph2, pw3*ph3);

            const __half2 z2  = __float2half2_rn(0.0f);
            const __half2 th3 = __float2half2_rn(3.0f);
            __half2 mac01 = __float2half2_rn(-60000.0f);
            __half2 mac23 = __float2half2_rn(-60000.0f);

            // margin = 3*inter - ga - pa; ignore iff margin > 0 (iou > 0.5)
            #pragma unroll
            for (int t = 0; t < TT; t++) {
                GtH g = s_gth[t];
                __half2 nga = s_nga[t];

                __half2 iw0 = __hmax2(__hsub2(__hmin2(g.rx, rX01), __hmax2(g.lx, lX01)), z2);
                __half2 ih0 = __hsub2(__hmin2(g.ry, rY01), __hmax2(g.ly, lY01));
                __half2 m0  = __hsub2(__hfma2(__hmul2(iw0, ih0), th3, nga), pa01);
                mac01 = __hmax2(mac01, m0);

                __half2 iw1 = __hmax2(__hsub2(__hmin2(g.rx, rX23), __hmax2(g.lx, lX23)), z2);
                __half2 ih1 = __hsub2(__hmin2(g.ry, rY23), __hmax2(g.ly, lY23));
                __half2 m1  = __hsub2(__hfma2(__hmul2(iw1, ih1), th3, nga), pa23);
                mac23 = __hmax2(mac23, m1);
            }

            float2 f01 = __half22float2(mac01);
            float2 f23 = __half22float2(mac23);

            // count every non-ignored cell as noobj; obj cells corrected by tgt path
            if (f01.x <= 0.0f) { cl += softplusf_(rc.x); cm += 1.0f; }
            if (f01.y <= 0.0f) { cl += softplusf_(rc.y); cm += 1.0f; }
            if (f23.x <= 0.0f) { cl += softplusf_(rc.z); cm += 1.0f; }
            if (f23.y <= 0.0f) { cl += softplusf_(rc.w); cm += 1.0f; }
        }

        #pragma unroll
        for (int o = 16; o > 0; o >>= 1) {
            cl += __shfl_down_sync(0xffffffffu, cl, o);
            cm += __shfl_down_sync(0xffffffffu, cm, o);
        }
        __shared__ float wcl[8], wcm[8];
        int wid = tid >> 5;
        if ((tid & 31) == 0) { wcl[wid] = cl; wcm[wid] = cm; }
        __syncthreads();
        if (tid == 0) {
            float scl = 0.0f, scm = 0.0f;
            #pragma unroll
            for (int k = 0; k < 8; k++) { scl += wcl[k]; scm += wcm[k]; }
            atomicAdd(&g_acc[3], (double)scl);
            atomicAdd(&g_acc[4], (double)scm);
        }
    } else {
        // ===== target path: one warp per target; ciou + cls + conf correction =====
        int t_idx = (blockIdx.x - MAIN_BLOCKS) * 8 + (tid >> 5);  // 0..639
        int lane  = tid & 31;

        float gx, gy, gw, gh;
        int cell = prep_target(tgt + t_idx * 5, gx, gy, gw, gh);

        if (cell >= 0) {
            int b   = t_idx / TT;
            int a   = cell / PLANE;
            int rem = cell - a * PLANE;
            const float* base = in + ((b * 255 + a * 85) * PLANE + rem);

            // class BCE: lanes cover 80 channels (<=3 each)
            int gc = (int)tgt[t_idx * 5 + 4];
            float cls = 0.0f;
            #pragma unroll
            for (int k = 0; k < 3; k++) {
                int ch = lane + 32 * k;
                if (ch < NC) {
                    float z = base[(5 + ch) * PLANE];
                    cls += (ch == gc) ? softplusf_(-z) : softplusf_(z);
                }
            }
            #pragma unroll
            for (int o = 16; o > 0; o >>= 1)
                cls += __shfl_down_sync(0xffffffffu, cls, o);

            if (lane == 0) {
                int i = rem % GW, j = rem / GW;
                float px = (float)i + sigmoidf_(base[0]);
                float py = (float)j + sigmoidf_(base[PLANE]);
                float pw = __expf(base[2 * PLANE]) * c_aw3[a];
                float ph = __expf(base[3 * PLANE]) * c_ah3[a];
                float rcv = base[4 * PLANE];

                float p0x = px - 0.5f * pw, p1x = px + 0.5f * pw;
                float p0y = py - 0.5f * ph, p1y = py + 0.5f * ph;
                float pa  = pw * ph;

                // ---- ciou vs matched gt (exact fp32) ----
                float q0x = gx - 0.5f * gw, q1x = gx + 0.5f * gw;
                float q0y = gy - 0.5f * gh, q1y = gy + 0.5f * gh;

                float iw = fmaxf(fminf(p1x, q1x) - fmaxf(p0x, q0x), 0.0f);
                float ih = fmaxf(fminf(p1y, q1y) - fmaxf(p0y, q0y), 0.0f);
                float inter = iw * ih;
                float uni = fmaxf(pa + gw * gh - inter, 1e-6f);
                float iou = inter / uni;

                float dx = px - gx, dy = py - gy;
                float cd = dx * dx + dy * dy;
                float ew = fmaxf(fmaxf(p1x, q1x) - fminf(p0x, q0x), 0.0f);
                float eh = fmaxf(fmaxf(p1y, q1y) - fminf(p0y, q0y), 0.0f);
                float diag = fmaxf(ew * ew + eh * eh, 1e-6f);
                float ciou = iou - cd / diag;

                float dv = atanf(pw / fmaxf(ph, 1e-6f)) - atanf(gw / fmaxf(gh, 1e-6f));
                float v = 0.4052847345693511f * dv * dv;   // 4/pi^2
                float alpha = v / fmaxf(1.0f - iou + v, 1e-6f);
                ciou -= alpha * v;

                // ---- conf correction: replace noobj contribution with obj ----
                bool ignc = false;
                const float* tb = tgt + b * TT * 5;
                #pragma unroll 1
                for (int t = 0; t < TT; t++) {
                    float tx = tb[t*5+0] * (float)GW, ty = tb[t*5+1] * (float)GW;
                    float tw = tb[t*5+2] * (float)GW, th = tb[t*5+3] * (float)GW;
                    float w0 = fmaxf(fminf(tx + 0.5f*tw, p1x) - fmaxf(tx - 0.5f*tw, p0x), 0.0f);
                    float h0 = fmaxf(fminf(ty + 0.5f*th, p1y) - fmaxf(ty - 0.5f*th, p0y), 0.0f);
                    ignc = ignc || (3.0f * w0 * h0 > tw * th + pa);
                }
                float dcl = softplusf_(-rcv) - (ignc ? 0.0f : softplusf_(rcv));
                float dcm = ignc ? 1.0f : 0.0f;

                atomicAdd(&g_acc[0], (double)(1.0f - ciou));
                atomicAdd(&g_acc[1], 1.0);
                atomicAdd(&g_acc[2], (double)cls);
                atomicAdd(&g_acc[3], (double)dcl);
                atomicAdd(&g_acc[4], (double)dcm);
            }
        }
    }

    finish_block(out);
}

extern "C" void kernel_launch(void* const* d_in, const int* in_sizes, int n_in,
                              void* d_out, int out_size) {
    const float* in  = (const float*)d_in[0];
    const float* tgt = (const float*)d_in[1];
    float* out = (float*)d_out;
    k_fused<<<GRID_TOT, 256>>>(in, tgt, out);
}

// round 15
// speedup vs baseline: 1.4332x; 1.4332x over previous
#include <cuda_runtime.h>
#include <math.h>
#include <stdint.h>

#define BS     32
#define TT     20               // targets per batch
#define GW     76               // grid width/height
#define PLANE  (GW*GW)          // 5776
#define QPB    (3*PLANE/4)      // cell-quads per batch = 4332
#define BPB    17               // blocks per batch
#define MAIN_BLOCKS (BS*BPB)    // 544
#define TGT_BLOCKS  80          // 80 x 8 warps = 640 warps = BS*TT
#define GRID_TOT (MAIN_BLOCKS + TGT_BLOCKS)  // 624
#define NC     80

// scaled anchors = ANCHORS / 8
__constant__ float c_aw9[9] = {1.5f, 2.375f, 5.0f, 4.5f, 9.5f, 9.0f, 17.75f, 24.0f, 57.375f};
__constant__ float c_ah9[9] = {2.0f, 4.5f,  3.5f, 9.375f, 6.875f, 18.25f, 13.75f, 30.375f, 50.125f};
// level-2 anchors (mask [0,1,2])
__constant__ float c_aw3[3] = {1.5f, 2.375f, 5.0f};
__constant__ float c_ah3[3] = {2.0f, 4.5f,  3.5f};

// zero-init at load; finalizer resets after each run (graph-replay safe)
__device__ double       g_acc[5];   // 0:loc 1:nobj 2:cls 3:conf 4:mask
__device__ unsigned int g_done;

__device__ __forceinline__ float softplusf_(float z) {
    float az = fabsf(z);
    return fmaxf(z, 0.0f) + __logf(1.0f + __expf(-az));
}
__device__ __forceinline__ float sigmoidf_(float x) {
    return __fdividef(1.0f, 1.0f + __expf(-x));
}

// prep one target: returns cell (-1 if not this level) and gt geometry
__device__ __forceinline__ int prep_target(const float* __restrict__ p,
                                           float& gx, float& gy, float& gw, float& gh) {
    gx = p[0] * (float)GW; gy = p[1] * (float)GW;
    gw = p[2] * (float)GW; gh = p[3] * (float)GW;
    float bestr = -1e30f; int best = 0;
    #pragma unroll
    for (int n = 0; n < 9; n++) {
        float inter = fminf(gw, c_aw9[n]) * fminf(gh, c_ah9[n]);
        float uni   = gw * gh + c_aw9[n] * c_ah9[n] - inter;
        float r = inter / uni;   // exact divide: argmax ties matter
        if (r > bestr) { bestr = r; best = n; }
    }
    if (best >= 3) return -1;    // l=2: anchors_mask [0,1,2]
    int gi = min(max((int)floorf(gx), 0), GW - 1);
    int gj = min(max((int)floorf(gy), 0), GW - 1);
    return best * PLANE + gj * GW + gi;
}

__device__ __forceinline__ void finish_block(float* out) {
    __syncthreads();
    if (threadIdx.x == 0) {
        __threadfence();
        unsigned int v = atomicAdd(&g_done, 1u);
        if (v == GRID_TOT - 1) {
            __threadfence();
            double a0 = g_acc[0], a1 = g_acc[1], a2 = g_acc[2];
            double a3 = g_acc[3], a4 = g_acc[4];
            g_acc[0]=0.0; g_acc[1]=0.0; g_acc[2]=0.0; g_acc[3]=0.0; g_acc[4]=0.0;
            g_done = 0u;
            double n     = a1 > 1.0 ? a1 : 1.0;
            double cmask = a4 > 1.0 ? a4 : 1.0;
            const double OBJ_RATIO = 5.0 * 608.0 * 608.0 / (416.0 * 416.0);
            const double BAL = 4.0;   // BALANCE[2]
            double loss = a0 / n * 0.05
                        + a2 / (n * (double)NC)
                        + a3 / cmask * BAL * OBJ_RATIO;
            out[0] = (float)loss;
        }
    }
}

__global__ void __launch_bounds__(256) k_fused(const float* __restrict__ in,
                                               const float* __restrict__ tgt,
                                               float* __restrict__ out)
{
    const int tid = threadIdx.x;

    if (blockIdx.x < MAIN_BLOCKS) {
        // ===== main path: noobj conf BCE; filtered exact ignore test =====
        __shared__ float4 s_box[TT];    // gt corners x0,y0,x1,y1
        __shared__ float  s_ar[TT];     // ga = gw*gh
        __shared__ float4 s_filt[TT];   // 0.5ga, 2ga, gy, 0.5gh

        const int b = blockIdx.x / BPB;
        const int q = (blockIdx.x % BPB) * 256 + tid;
        const bool act = (q < QPB);

        if (tid < TT) {
            const float* p = tgt + (b * TT + tid) * 5;
            float gx = p[0] * (float)GW, gy = p[1] * (float)GW;
            float gw = p[2] * (float)GW, gh = p[3] * (float)GW;
            float ga = gw * gh;
            s_box[tid]  = make_float4(gx - 0.5f * gw, gy - 0.5f * gh,
                                      gx + 0.5f * gw, gy + 0.5f * gh);
            s_ar[tid]   = ga;
            s_filt[tid] = make_float4(0.5f * ga, 2.0f * ga, gy, 0.5f * gh);
        }
        __syncthreads();

        // decode (guarded), filter, then warp-union the survivor set
        float px0,px1,px2,px3, py0,py1,py2,py3;
        float l0x,l1x,l2x,l3x, r0x,r1x,r2x,r3x;
        float l0y,l1y,l2y,l3y, r0y,r1y,r2y,r3y;
        float pa0,pa1,pa2,pa3;
        float4 rc = make_float4(0.f,0.f,0.f,0.f);
        unsigned bits = 0u;

        if (act) {
            int c0  = 4 * q;
            int a   = c0 / PLANE;
            int rem = c0 - a * PLANE;            // multiple of 4; row-aligned (GW%4==0)
            int j   = rem / GW;
            int i0  = rem - j * GW;

            const float* base = in + ((b * 255 + a * 85) * PLANE + rem);
            float4 rx = *(const float4*)(base);
            float4 ry = *(const float4*)(base + PLANE);
            float4 rw = *(const float4*)(base + 2 * PLANE);
            float4 rh = *(const float4*)(base + 3 * PLANE);
            rc        = *(const float4*)(base + 4 * PLANE);

            const float aw = c_aw3[a], ah = c_ah3[a];
            const float fj = (float)j;

            px0 = (float)(i0+0) + sigmoidf_(rx.x);
            px1 = (float)(i0+1) + sigmoidf_(rx.y);
            px2 = (float)(i0+2) + sigmoidf_(rx.z);
            px3 = (float)(i0+3) + sigmoidf_(rx.w);
            py0 = fj + sigmoidf_(ry.x);
            py1 = fj + sigmoidf_(ry.y);
            py2 = fj + sigmoidf_(ry.z);
            py3 = fj + sigmoidf_(ry.w);
            float pw0 = __expf(rw.x) * aw, pw1 = __expf(rw.y) * aw;
            float pw2 = __expf(rw.z) * aw, pw3 = __expf(rw.w) * aw;
            float ph0 = __expf(rh.x) * ah, ph1 = __expf(rh.y) * ah;
            float ph2 = __expf(rh.z) * ah, ph3 = __expf(rh.w) * ah;

            l0x = px0 - 0.5f*pw0; r0x = px0 + 0.5f*pw0;
            l1x = px1 - 0.5f*pw1; r1x = px1 + 0.5f*pw1;
            l2x = px2 - 0.5f*pw2; r2x = px2 + 0.5f*pw2;
            l3x = px3 - 0.5f*pw3; r3x = px3 + 0.5f*pw3;
            l0y = py0 - 0.5f*ph0; r0y = py0 + 0.5f*ph0;
            l1y = py1 - 0.5f*ph1; r1y = py1 + 0.5f*ph1;
            l2y = py2 - 0.5f*ph2; r2y = py2 + 0.5f*ph2;
            l3y = py3 - 0.5f*ph3; r3y = py3 + 0.5f*ph3;
            pa0 = pw0*ph0; pa1 = pw1*ph1; pa2 = pw2*ph2; pa3 = pw3*ph3;

            float pamax = fmaxf(fmaxf(pa0, pa1), fmaxf(pa2, pa3));
            float pamin = fminf(fminf(pa0, pa1), fminf(pa2, pa3));
            float phmax = fmaxf(fmaxf(ph0, ph1), fmaxf(ph2, ph3));
            float cy = fj + 0.5f;
            float yb = 0.5f * phmax + 0.5f;

            // necessary-condition filter (sound):
            //  trigger => pa > ga/2 && pa < 2ga && |gy - (j+.5)| < .5gh + .5ph + .5
            #pragma unroll
            for (int t = 0; t < TT; t++) {
                float4 f = s_filt[t];
                bool p = (pamax > f.x) & (pamin < f.y)
                       & (fabsf(f.z - cy) < f.w + yb);
                bits |= (p ? 1u : 0u) << t;
            }
        }

        // warp-union so the exact loop is non-divergent (all threads participate)
        unsigned ubits = __reduce_or_sync(0xffffffffu, bits);

        float cl = 0.0f, cm = 0.0f;
        if (act) {
            float m0 = -1e30f, m1 = -1e30f, m2 = -1e30f, m3 = -1e30f;
            while (ubits) {
                int t = __ffs(ubits) - 1;
                ubits &= ubits - 1u;
                float4 bb = s_box[t];
                float nga = -s_ar[t];

                float iw0 = fmaxf(fminf(bb.z, r0x) - fmaxf(bb.x, l0x), 0.0f);
                float ih0 = fminf(bb.w, r0y) - fmaxf(bb.y, l0y);
                m0 = fmaxf(m0, fmaf(3.0f, iw0*ih0, nga - pa0));

                float iw1 = fmaxf(fminf(bb.z, r1x) - fmaxf(bb.x, l1x), 0.0f);
                float ih1 = fminf(bb.w, r1y) - fmaxf(bb.y, l1y);
                m1 = fmaxf(m1, fmaf(3.0f, iw1*ih1, nga - pa1));

                float iw2 = fmaxf(fminf(bb.z, r2x) - fmaxf(bb.x, l2x), 0.0f);
                float ih2 = fminf(bb.w, r2y) - fmaxf(bb.y, l2y);
                m2 = fmaxf(m2, fmaf(3.0f, iw2*ih2, nga - pa2));

                float iw3 = fmaxf(fminf(bb.z, r3x) - fmaxf(bb.x, l3x), 0.0f);
                float ih3 = fminf(bb.w, r3y) - fmaxf(bb.y, l3y);
                m3 = fmaxf(m3, fmaf(3.0f, iw3*ih3, nga - pa3));
            }
            // note: ih unclamped is safe — iw clamped to 0 kills negative-extent cells,
            // and iw>0 with ih<0 gives negative product (never > 0 threshold)

            // count every non-ignored cell as noobj; obj cells corrected by tgt path
            if (m0 <= 0.0f) { cl += softplusf_(rc.x); cm += 1.0f; }
            if (m1 <= 0.0f) { cl += softplusf_(rc.y); cm += 1.0f; }
            if (m2 <= 0.0f) { cl += softplusf_(rc.z); cm += 1.0f; }
            if (m3 <= 0.0f) { cl += softplusf_(rc.w); cm += 1.0f; }
        }

        #pragma unroll
        for (int o = 16; o > 0; o >>= 1) {
            cl += __shfl_down_sync(0xffffffffu, cl, o);
            cm += __shfl_down_sync(0xffffffffu, cm, o);
        }
        __shared__ float wcl[8], wcm[8];
        int wid = tid >> 5;
        if ((tid & 31) == 0) { wcl[wid] = cl; wcm[wid] = cm; }
        __syncthreads();
        if (tid == 0) {
            float scl = 0.0f, scm = 0.0f;
            #pragma unroll
            for (int k = 0; k < 8; k++) { scl += wcl[k]; scm += wcm[k]; }
            atomicAdd(&g_acc[3], (double)scl);
            atomicAdd(&g_acc[4], (double)scm);
        }
    } else {
        // ===== target path: one warp per target; ciou + cls + conf correction =====
        int t_idx = (blockIdx.x - MAIN_BLOCKS) * 8 + (tid >> 5);  // 0..639
        int lane  = tid & 31;

        float gx, gy, gw, gh;
        int cell = prep_target(tgt + t_idx * 5, gx, gy, gw, gh);

        if (cell >= 0) {
            int b   = t_idx / TT;
            int a   = cell / PLANE;
            int rem = cell - a * PLANE;
            const float* base = in + ((b * 255 + a * 85) * PLANE + rem);

            // class BCE: lanes cover 80 channels (<=3 each)
            int gc = (int)tgt[t_idx * 5 + 4];
            float cls = 0.0f;
            #pragma unroll
            for (int k = 0; k < 3; k++) {
                int ch = lane + 32 * k;
                if (ch < NC) {
                    float z = base[(5 + ch) * PLANE];
                    cls += (ch == gc) ? softplusf_(-z) : softplusf_(z);
                }
            }
            #pragma unroll
            for (int o = 16; o > 0; o >>= 1)
                cls += __shfl_down_sync(0xffffffffu, cls, o);

            if (lane == 0) {
                int i = rem % GW, j = rem / GW;
                float px = (float)i + sigmoidf_(base[0]);
                float py = (float)j + sigmoidf_(base[PLANE]);
                float pw = __expf(base[2 * PLANE]) * c_aw3[a];
                float ph = __expf(base[3 * PLANE]) * c_ah3[a];
                float rcv = base[4 * PLANE];

                float p0x = px - 0.5f * pw, p1x = px + 0.5f * pw;
                float p0y = py - 0.5f * ph, p1y = py + 0.5f * ph;
                float pa  = pw * ph;

                // ---- ciou vs matched gt (exact fp32) ----
                float q0x = gx - 0.5f * gw, q1x = gx + 0.5f * gw;
                float q0y = gy - 0.5f * gh, q1y = gy + 0.5f * gh;

                float iw = fmaxf(fminf(p1x, q1x) - fmaxf(p0x, q0x), 0.0f);
                float ih = fmaxf(fminf(p1y, q1y) - fmaxf(p0y, q0y), 0.0f);
                float inter = iw * ih;
                float uni = fmaxf(pa + gw * gh - inter, 1e-6f);
                float iou = inter / uni;

                float dx = px - gx, dy = py - gy;
                float cd = dx * dx + dy * dy;
                float ew = fmaxf(fmaxf(p1x, q1x) - fminf(p0x, q0x), 0.0f);
                float eh = fmaxf(fmaxf(p1y, q1y) - fminf(p0y, q0y), 0.0f);
                float diag = fmaxf(ew * ew + eh * eh, 1e-6f);
                float ciou = iou - cd / diag;

                float dv = atanf(pw / fmaxf(ph, 1e-6f)) - atanf(gw / fmaxf(gh, 1e-6f));
                float v = 0.4052847345693511f * dv * dv;   // 4/pi^2
                float alpha = v / fmaxf(1.0f - iou + v, 1e-6f);
                ciou -= alpha * v;

                // ---- conf correction: replace noobj contribution with obj ----
                bool ignc = false;
                const float* tb = tgt + b * TT * 5;
                #pragma unroll 1
                for (int t = 0; t < TT; t++) {
                    float tx = tb[t*5+0] * (float)GW, ty = tb[t*5+1] * (float)GW;
                    float tw = tb[t*5+2] * (float)GW, th = tb[t*5+3] * (float)GW;
                    float w0 = fmaxf(fminf(tx + 0.5f*tw, p1x) - fmaxf(tx - 0.5f*tw, p0x), 0.0f);
                    float h0 = fmaxf(fminf(ty + 0.5f*th, p1y) - fmaxf(ty - 0.5f*th, p0y), 0.0f);
                    ignc = ignc || (3.0f * w0 * h0 > tw * th + pa);
                }
                float dcl = softplusf_(-rcv) - (ignc ? 0.0f : softplusf_(rcv));
                float dcm = ignc ? 1.0f : 0.0f;

                atomicAdd(&g_acc[0], (double)(1.0f - ciou));
                atomicAdd(&g_acc[1], 1.0);
                atomicAdd(&g_acc[2], (double)cls);
                atomicAdd(&g_acc[3], (double)dcl);
                atomicAdd(&g_acc[4], (double)dcm);
            }
        }
    }

    finish_block(out);
}

extern "C" void kernel_launch(void* const* d_in, const int* in_sizes, int n_in,
                              void* d_out, int out_size) {
    const float* in  = (const float*)d_in[0];
    const float* tgt = (const float*)d_in[1];
    float* out = (float*)d_out;
    k_fused<<<GRID_TOT, 256>>>(in, tgt, out);
}